// round 17
// baseline (speedup 1.0000x reference)
#include <cuda_runtime.h>

#define BATCH 512
#define TLEN 16385
#define NN 16384
#define THREADS 256
#define HALF 8192
#define NWARP 8
#define PADL(j) ((j) + (((j) >> 5) << 2))      // xs pad 4 per 32
#define XS_WORDS 9220                          // PADL(8192)+1=9217 -> 16B pad
#define PADQ(q) ((q) + ((q) >> 3))             // group pad 1 per 8
#define CHKH_WORDS 2304                        // PADQ(2047)+2 rounded
#define SMEM_TOT (XS_WORDS + 2 * CHKH_WORDS)   // 13828 floats = 55.3KB

__device__ __forceinline__ float fsqrt_a(float v) {
    float r; asm("sqrt.approx.f32 %0, %1;" : "=f"(r) : "f"(v)); return r;
}
__device__ __forceinline__ float fex2_a(float v) {
    float r; asm("ex2.approx.f32 %0, %1;" : "=f"(r) : "f"(v)); return r;
}
__device__ __forceinline__ float flg2_a(float v) {
    float r; asm("lg2.approx.f32 %0, %1;" : "=f"(r) : "f"(v)); return r;
}

__device__ __forceinline__ float warp_iscan(float v, unsigned lane) {
    #pragma unroll
    for (int d = 1; d < 32; d <<= 1) {
        float n = __shfl_up_sync(0xffffffffu, v, d);
        if (lane >= d) v += n;
    }
    return v;
}

// Stage half row into padded smem AND emit per-group trapezoid integrals.
// Row phase P = b&3 (x[j] at global idx b*16385+j === b+j mod 4).
// Group q covers x_h[4q..4q+3]; nx = x_h[4q+4] (slot P of W1).
template <int P>
__device__ __forceinline__ void stage_vec(float* xs, float* gs,
                                          const float* __restrict__ xh, int tid) {
    const float4* __restrict__ vec = (const float4*)(xh - P);
    #pragma unroll
    for (int k = 0; k < 8; k++) {
        const int q = k * THREADS + tid;            // group in [0,2048)
        float4 W0 = __ldg(vec + q);
        float4 W1 = __ldg(vec + q + 1);             // overlaps lane+1's W0
        float e0, e1, e2, e3, nx;
        if (P == 0) { e0=W0.x; e1=W0.y; e2=W0.z; e3=W0.w; nx=W1.x; }
        if (P == 1) { e0=W0.y; e1=W0.z; e2=W0.w; e3=W1.x; nx=W1.y; }
        if (P == 2) { e0=W0.z; e1=W0.w; e2=W1.x; e3=W1.y; nx=W1.z; }
        if (P == 3) { e0=W0.w; e1=W1.x; e2=W1.y; e3=W1.z; nx=W1.w; }
        *(float4*)(xs + PADL(4 * q)) = make_float4(e0, e1, e2, e3);
        gs[PADQ(q)] = 0.5f * (e0 + nx) + ((e1 + e2) + e3);   // group trapz
    }
    if (tid == 0) xs[PADL(HALF)] = xh[HALF];
}

__device__ __forceinline__ void stage_dispatch(float* xs, float* gs,
                                               const float* xh, int tid, int P) {
    switch (P) {
        case 0:  stage_vec<0>(xs, gs, xh, tid); break;
        case 1:  stage_vec<1>(xs, gs, xh, tid); break;
        case 2:  stage_vec<2>(xs, gs, xh, tid); break;
        default: stage_vec<3>(xs, gs, xh, tid); break;
    }
}

// Direct-gmem output for half 0 via 5-elem windows (R15-verified pattern):
// u_k = chk[f] + 0.5*x0 + lps - 0.5*xc.
template <int P>
__device__ __forceinline__ void out_h0(const float* __restrict__ xr,
                                       const float* __restrict__ chk0,
                                       float c0, float c1, float r, bool rhalf,
                                       float4* __restrict__ xh4,
                                       float4* __restrict__ rs4, int tid)
{
    const float4* __restrict__ vec = (const float4*)(xr - P);
    #pragma unroll
    for (int g = 0; g < 8; g++) {
        const int f = g * THREADS + tid;            // chunk in [0,2048), half 0
        float4 W0 = __ldg(vec + f);
        float4 W1 = __ldg(vec + f + 1);
        float x0, e[4];
        if (P == 0) { x0=W0.x; e[0]=W0.y; e[1]=W0.z; e[2]=W0.w; e[3]=W1.x; }
        if (P == 1) { x0=W0.y; e[0]=W0.z; e[1]=W0.w; e[2]=W1.x; e[3]=W1.y; }
        if (P == 2) { x0=W0.z; e[0]=W0.w; e[1]=W1.x; e[2]=W1.y; e[3]=W1.z; }
        if (P == 3) { x0=W0.w; e[0]=W1.x; e[1]=W1.y; e[2]=W1.z; e[3]=W1.w; }
        const float cb = chk0[PADQ(f)] + 0.5f * x0;
        float hv[4], rv[4];
        float lps = 0.f;
        #pragma unroll
        for (int m = 0; m < 4; m++) {
            float xc = e[m];
            lps += xc;
            float u  = fmaf(-0.5f, xc, cb + lps);
            float su = rhalf ? fsqrt_a(u) : fex2_a(r * flg2_a(u));
            float xh = fmaf(c0, u, c1 * su);
            hv[m] = xh; rv[m] = xc - xh;
        }
        xh4[f] = make_float4(hv[0], hv[1], hv[2], hv[3]);
        rs4[f] = make_float4(rv[0], rv[1], rv[2], rv[3]);
    }
}

__global__ __launch_bounds__(THREADS, 4)
void vp_kernel(const float* __restrict__ x, const float* __restrict__ params,
               float* __restrict__ o_coeffs, float* __restrict__ o_xhat,
               float* __restrict__ o_res, float* __restrict__ o_r2)
{
    extern __shared__ __align__(16) float smem[];
    float* xs  = smem;                        // staged half row (padded)
    float* chk = smem + XS_WORDS;             // group sums -> checkpoints, 2 halves
    __shared__ float warp_tot[NWARP];
    __shared__ float red[NWARP * 6];

    const int tid  = threadIdx.x;
    const int lane = tid & 31;
    const int wid  = tid >> 5;
    const int b    = blockIdx.x;
    const float* __restrict__ xr = x + (size_t)b * TLEN;
    const float r  = params[0];
    const float ny = params[1];
    const bool rhalf = (r == 0.5f);
    const int P = b & 3;

    // blocked views: thread owns x_h[32t..32t+32] = groups 8t..8t+7
    const float4* __restrict__ xt4 = (const float4*)(xs + 36 * tid);
    const int blast = 36 * tid + 36;
    const int qb9   = 9 * tid;                // PADQ(8t)

    float uoff = ny;
    float sA = 0.f, sB = 0.f, sC = 0.f, sD0 = 0.f, sD1 = 0.f, sE = 0.f;

    // ================= Both halves: stage+groupsum -> scan -> sums ========
    #pragma unroll 1
    for (int h = 0; h < 2; h++) {
        float* chkh = chk + h * CHKH_WORDS;
        stage_dispatch(xs, chkh, xr + h * HALF, tid, P);
        __syncthreads();

        // thread-local scan over its 8 blocked group sums (stride-9, no conflicts)
        float pre[8];
        float runv = 0.f;
        #pragma unroll
        for (int i = 0; i < 8; i++) {
            float v = chkh[qb9 + i];
            pre[i] = runv;
            runv += v;
        }
        float incw = warp_iscan(runv, lane);
        if (lane == 31) warp_tot[wid] = incw;
        __syncthreads();
        // redundant cross-warp prefix (every thread; no wid==0 block)
        float wpre = 0.f, wall = 0.f;
        #pragma unroll
        for (int w = 0; w < NWARP; w++) {
            float v = warp_tot[w];
            if (w < wid) wpre += v;
            wall += v;
        }
        const float base = uoff + (incw - runv) + wpre;
        #pragma unroll
        for (int i = 0; i < 8; i++) chkh[qb9 + i] = base + pre[i];
        uoff += wall;

        // Gram/data sums; cb per group from chk (no serial ps chain)
        float4 cur = xt4[0];
        #pragma unroll
        for (int g = 0; g < 8; g++) {
            float4 nxt;
            if (g < 7) nxt = xt4[g + 1];
            else { nxt.x = xs[blast]; nxt.y = nxt.z = nxt.w = 0.f; }
            const float cb2 = chkh[qb9 + g] + 0.5f * cur.x;
            float e[4] = {cur.y, cur.z, cur.w, nxt.x};
            float lps = 0.f;
            #pragma unroll
            for (int m = 0; m < 4; m++) {
                float xc = e[m];
                lps += xc;
                float u  = fmaf(-0.5f, xc, cb2 + lps);
                float su = rhalf ? fsqrt_a(u) : fex2_a(r * flg2_a(u));
                sA  = fmaf(u, u, sA);
                sB  = fmaf(u, su, sB);
                sC += u;
                sD0 = fmaf(xc, u, sD0);
                sD1 = fmaf(xc, su, sD1);
                sE  = fmaf(xc, xc, sE);
            }
            cur = nxt;
        }
        if (h == 0) __syncthreads();         // xs/warp_tot reuse by half 1
    }

    // ================= Block reduce + redundant fp32 rank-1 solve ==========
    #pragma unroll
    for (int d = 16; d; d >>= 1) {
        sA  += __shfl_xor_sync(~0u, sA,  d);
        sB  += __shfl_xor_sync(~0u, sB,  d);
        sC  += __shfl_xor_sync(~0u, sC,  d);
        sD0 += __shfl_xor_sync(~0u, sD0, d);
        sD1 += __shfl_xor_sync(~0u, sD1, d);
        sE  += __shfl_xor_sync(~0u, sE,  d);
    }
    if (lane == 0) {
        red[wid * 6 + 0] = sA;  red[wid * 6 + 1] = sB;
        red[wid * 6 + 2] = sC;  red[wid * 6 + 3] = sD0;
        red[wid * 6 + 4] = sD1; red[wid * 6 + 5] = sE;
    }
    __syncthreads();

    // JAX pinv rcond = 10*max(M,N)*eps truncates sigma_2 -> rank-1 solve.
    float c0, c1;
    {
        float A = 0.f, Bb = 0.f, C = 0.f, D0 = 0.f, D1 = 0.f, E = 0.f;
        #pragma unroll
        for (int w = 0; w < NWARP; w++) {
            A  += red[w * 6 + 0]; Bb += red[w * 6 + 1];
            C  += red[w * 6 + 2]; D0 += red[w * 6 + 3];
            D1 += red[w * 6 + 4]; E  += red[w * 6 + 5];
        }
        float hh  = 0.5f * (A - C);
        float s   = sqrtf(fmaf(hh, hh, Bb * Bb));
        float lam = 0.5f * (A + C) + s;          // lambda_1 of Gram
        float w0  = Bb;
        float w1  = Bb * Bb / (hh + s);          // = lam - A, stable form
        float n2  = fmaf(w0, w0, w1 * w1);
        float beta = fmaf(w0, D0, w1 * D1) / (lam * n2);
        c0 = beta * w0;
        c1 = beta * w1;
        if (tid == 0) {
            o_coeffs[b * 2 + 0] = c0;
            o_coeffs[b * 2 + 1] = c1;
            // analytic r2 = E - 2 c.d + c^T G c  (G = [[A,Bb],[Bb,C]])
            float r2 = E - 2.f * fmaf(c0, D0, c1 * D1)
                     + (c0 * c0 * A + 2.f * c0 * c1 * Bb + c1 * c1 * C);
            o_r2[b] = r2;
        }
    }

    // ================= Outputs =================
    float4* __restrict__ xh4 = (float4*)(o_xhat + (size_t)b * NN);
    float4* __restrict__ rs4 = (float4*)(o_res  + (size_t)b * NN);

    // --- half 0: direct gmem windows (no restage) ---
    switch (P) {
        case 0:  out_h0<0>(xr, chk, c0, c1, r, rhalf, xh4, rs4, tid); break;
        case 1:  out_h0<1>(xr, chk, c0, c1, r, rhalf, xh4, rs4, tid); break;
        case 2:  out_h0<2>(xr, chk, c0, c1, r, rhalf, xh4, rs4, tid); break;
        default: out_h0<3>(xr, chk, c0, c1, r, rhalf, xh4, rs4, tid); break;
    }

    // --- half 1: from resident smem (still holds half 1) ---
    {
        const float* chk1 = chk + CHKH_WORDS;
        const float4* __restrict__ xs4 = (const float4*)xs;
        #pragma unroll
        for (int g = 0; g < 8; g++) {
            const int f = g * THREADS + tid;           // local chunk in half 1
            float4 v = xs4[f + (f >> 3)];              // padded float4 view
            float nx = __shfl_down_sync(0xffffffffu, v.x, 1);
            if (lane == 31) nx = xs[PADL(4 * f + 4)];  // warp-edge boundary
            const float cb = chk1[PADQ(f)] + 0.5f * v.x;
            float e[4] = {v.y, v.z, v.w, nx};
            float hv[4], rv[4];
            float pl = 0.f;
            #pragma unroll
            for (int m = 0; m < 4; m++) {
                float xc = e[m];
                pl += xc;
                float u  = fmaf(-0.5f, xc, cb + pl);
                float su = rhalf ? fsqrt_a(u) : fex2_a(r * flg2_a(u));
                float xv = fmaf(c0, u, c1 * su);
                hv[m] = xv; rv[m] = xc - xv;
            }
            const int o4 = 2048 + f;
            xh4[o4] = make_float4(hv[0], hv[1], hv[2], hv[3]);
            rs4[o4] = make_float4(rv[0], rv[1], rv[2], rv[3]);
        }
    }
}

extern "C" void kernel_launch(void* const* d_in, const int* in_sizes, int n_in,
                              void* d_out, int out_size)
{
    const float* x      = (const float*)d_in[0];
    const float* params = (const float*)d_in[1];
    if (n_in >= 2 && in_sizes[0] == 2) {       // defensive: metadata order swap
        x      = (const float*)d_in[1];
        params = (const float*)d_in[0];
    }
    float* out      = (float*)d_out;
    float* o_coeffs = out;                                   // 512*1*2
    float* o_xhat   = out + (size_t)BATCH * 2;               // 512*1*16384
    float* o_res    = o_xhat + (size_t)BATCH * NN;           // 512*1*16384
    float* o_r2     = o_res  + (size_t)BATCH * NN;           // 512*1

    size_t smem = SMEM_TOT * sizeof(float);
    cudaFuncSetAttribute(vp_kernel, cudaFuncAttributeMaxDynamicSharedMemorySize,
                         (int)smem);
    vp_kernel<<<BATCH, THREADS, smem>>>(x, params, o_coeffs, o_xhat, o_res, o_r2);
}